// round 10
// baseline (speedup 1.0000x reference)
#include <cuda_runtime.h>
#include <cuda_bf16.h>
#include <math.h>

#define B_ 2
#define S_ 4096
#define E_ 1024
#define D_ 64
#define WIN_ 5
#define DIL_ 2

// Scratch (allocation-free rule: __device__ globals)
__device__ float g_Q[B_ * S_ * D_];
__device__ float g_K[B_ * S_ * D_];
__device__ float g_V[B_ * S_ * D_];
__device__ float g_Vsum[B_ * D_];
// W merged+split: [k/2][col], col = mat*64 + n, packed bf16 pairs {2k2, 2k2+1}
__device__ unsigned g_Wbhi[(E_ / 2) * 192];
__device__ unsigned g_Wblo[(E_ / 2) * 192];

// ---------------------------------------------------------------------------
// bf16 helpers
// ---------------------------------------------------------------------------
__device__ __forceinline__ unsigned pack_bf16(float lo_val, float hi_val) {
    __nv_bfloat162 p;
    p.x = __float2bfloat16(lo_val);
    p.y = __float2bfloat16(hi_val);
    return *(unsigned*)&p;
}
__device__ __forceinline__ float bf_residual(float v) {
    __nv_bfloat16 h = __float2bfloat16(v);
    return v - __bfloat162float(h);
}
__device__ __forceinline__ void mma_bf16(float* c, const unsigned* a, const unsigned* b) {
    asm volatile(
        "mma.sync.aligned.m16n8k16.row.col.f32.bf16.bf16.f32 "
        "{%0,%1,%2,%3}, {%4,%5,%6,%7}, {%8,%9}, {%0,%1,%2,%3};"
        : "+f"(c[0]), "+f"(c[1]), "+f"(c[2]), "+f"(c[3])
        : "r"(a[0]), "r"(a[1]), "r"(a[2]), "r"(a[3]), "r"(b[0]), "r"(b[1]));
}

// ---------------------------------------------------------------------------
// Kernel 0: W -> merged packed bf16 hi/lo planes, [k/2][mat*64+n].
// Also initializes g_Vsum with the bias contribution: S * bv[d].
// ---------------------------------------------------------------------------
__global__ void wsplit_kernel(const float* __restrict__ Wq,
                              const float* __restrict__ Wk,
                              const float* __restrict__ Wv,
                              const float* __restrict__ bv)
{
    const int idx = blockIdx.x * blockDim.x + threadIdx.x;
    if (blockIdx.x == 0 && threadIdx.x < B_ * D_) {
        g_Vsum[threadIdx.x] = (float)S_ * bv[threadIdx.x & (D_ - 1)];
    }
    if (idx >= (E_ / 2) * 192) return;
    const int k2 = idx / 192;
    const int c  = idx - k2 * 192;
    const int mat = c >> 6;
    const int n = c & 63;
    const float* src = (mat == 0) ? Wq : (mat == 1) ? Wk : Wv;
    const float v0 = src[(2 * k2) * D_ + n];
    const float v1 = src[(2 * k2 + 1) * D_ + n];
    g_Wbhi[idx] = pack_bf16(v0, v1);
    g_Wblo[idx] = pack_bf16(bf_residual(v0), bf_residual(v1));
}

// ---------------------------------------------------------------------------
// Kernel 1: MERGED QKV GEMM, 3xBF16 (hh+lh+hl) on m16n8k16, BK=32.
// C[8192 x 192] = x @ [Wq|Wk|Wv] + bias. BM=64, 512 thr = 16 warps (4m x 4n),
// warp tile 16x48 -> 4 warps/SMSP for latency hiding. 36 MMAs/warp/K-tile,
// 32 K-tiles. V-column sums fused in epilogue (shfl + atomicAdd).
// ---------------------------------------------------------------------------
#define BM 64
#define SA 20     // As row stride (u32): banks (20r+kc)%32 all distinct
#define SB 200    // Bs row stride (u32): banks (8kc+n)%32 all distinct

// u32 offsets in dynamic smem
#define OFF_AH(s) ((s) * 1280)
#define OFF_AL(s) (2560 + (s) * 1280)
#define OFF_BH(s) (5120 + (s) * 3200)
#define OFF_BL(s) (11520 + (s) * 3200)
#define SMEM_U32  17920

__global__ __launch_bounds__(512) void qkv_gemm_merged(
    const float* __restrict__ x,
    const float* __restrict__ bq,
    const float* __restrict__ bk,
    const float* __restrict__ bv)
{
    extern __shared__ unsigned sm[];

    const int tid  = threadIdx.x;
    const int lane = tid & 31;
    const int wid  = tid >> 5;
    const int wm   = wid >> 2;      // 0..3 -> m0 = wm*16
    const int wn   = wid & 3;       // 0..3 -> n0 = wn*48
    const int rowBase = blockIdx.x * BM;
    const int bb = rowBase >> 12;   // batch of this block

    // A global: 64 rows x 8 float4 slots = 512 -> exactly 1 float4/thread
    const int arow = tid >> 3;          // 0..63
    const int af   = tid & 7;           // 0..7
    const float* aptr = x + (size_t)(rowBase + arow) * E_ + af * 4;

    float acc[6][4];
#pragma unroll
    for (int nt = 0; nt < 6; nt++)
#pragma unroll
        for (int k = 0; k < 4; k++) acc[nt][k] = 0.f;

    const int r  = lane >> 2;
    const int cc = lane & 3;
    const int m0 = wm * 16;
    const int n0 = wn * 48;

    float4 pa;
    uint2 pbh[3], pbl[3];

    auto load_tile = [&](int kt) {
        pa = *(const float4*)(aptr + kt * 32);
        // B: plane = 16 k2-rows x 96 uint2 = 1536 uint2; 512 threads x 3
        const unsigned* wh = g_Wbhi + (size_t)kt * 16 * 192;
        const unsigned* wl = g_Wblo + (size_t)kt * 16 * 192;
#pragma unroll
        for (int i = 0; i < 3; i++) {
            const int e = tid + 512 * i;        // 0..1535
            pbh[i] = *(const uint2*)(wh + e * 2);
            pbl[i] = *(const uint2*)(wl + e * 2);
        }
    };

    auto store_tile = [&](int st) {
        uint2 h, l;
        h.x = pack_bf16(pa.x, pa.y);
        h.y = pack_bf16(pa.z, pa.w);
        l.x = pack_bf16(bf_residual(pa.x), bf_residual(pa.y));
        l.y = pack_bf16(bf_residual(pa.z), bf_residual(pa.w));
        *(uint2*)&sm[OFF_AH(st) + arow * SA + af * 2] = h;
        *(uint2*)&sm[OFF_AL(st) + arow * SA + af * 2] = l;
#pragma unroll
        for (int i = 0; i < 3; i++) {
            const int e = tid + 512 * i;
            const int krow = e / 96;
            const int cu2 = e - krow * 96;
            *(uint2*)&sm[OFF_BH(st) + krow * SB + cu2 * 2] = pbh[i];
            *(uint2*)&sm[OFF_BL(st) + krow * SB + cu2 * 2] = pbl[i];
        }
    };

    auto compute_tile = [&](int st) {
        const unsigned* AH = sm + OFF_AH(st);
        const unsigned* AL = sm + OFF_AL(st);
        const unsigned* BH = sm + OFF_BH(st);
        const unsigned* BL = sm + OFF_BL(st);
#pragma unroll
        for (int ks = 0; ks < 2; ks++) {
            const int kc = ks * 8 + cc;
            const int mr = m0 + r;
            unsigned ah[4], al[4];
            ah[0] = AH[mr * SA + kc];
            ah[1] = AH[(mr + 8) * SA + kc];
            ah[2] = AH[mr * SA + kc + 4];
            ah[3] = AH[(mr + 8) * SA + kc + 4];
            al[0] = AL[mr * SA + kc];
            al[1] = AL[(mr + 8) * SA + kc];
            al[2] = AL[mr * SA + kc + 4];
            al[3] = AL[(mr + 8) * SA + kc + 4];

            unsigned bh[6][2], bl[6][2];
#pragma unroll
            for (int nt = 0; nt < 6; nt++) {
                const int n = n0 + nt * 8 + r;
                bh[nt][0] = BH[kc * SB + n];
                bh[nt][1] = BH[(kc + 4) * SB + n];
                bl[nt][0] = BL[kc * SB + n];
                bl[nt][1] = BL[(kc + 4) * SB + n];
            }
#pragma unroll
            for (int nt = 0; nt < 6; nt++) mma_bf16(acc[nt], ah, bh[nt]);
#pragma unroll
            for (int nt = 0; nt < 6; nt++) mma_bf16(acc[nt], al, bh[nt]);
#pragma unroll
            for (int nt = 0; nt < 6; nt++) mma_bf16(acc[nt], ah, bl[nt]);
        }
    };

    load_tile(0);
    store_tile(0);
    __syncthreads();

    const int KTILES = E_ / 32;   // 32
    for (int kt = 1; kt < KTILES; kt++) {
        load_tile(kt);
        compute_tile((kt - 1) & 1);
        store_tile(kt & 1);            // other buffer: fenced by previous sync
        __syncthreads();
    }
    compute_tile((KTILES - 1) & 1);

    // epilogue: route 8-col groups to Q/K/V with bias; fuse V column sums
#pragma unroll
    for (int nt = 0; nt < 6; nt++) {
        const int colbase = n0 + nt * 8;
        const int mat = colbase >> 6;
        const int ocolb = colbase & 63;
        float* op = (mat == 0) ? g_Q : (mat == 1) ? g_K : g_V;
        const float* bp = (mat == 0) ? bq : (mat == 1) ? bk : bv;
        const int ocol = ocolb + 2 * cc;
        const float b0v = bp[ocol];
        const float b1v = bp[ocol + 1];
        const int row0 = rowBase + m0 + r;
        float2 v0 = make_float2(acc[nt][0] + b0v, acc[nt][1] + b1v);
        float2 v1 = make_float2(acc[nt][2] + b0v, acc[nt][3] + b1v);
        *(float2*)&op[(size_t)row0 * D_ + ocol] = v0;
        *(float2*)&op[(size_t)(row0 + 8) * D_ + ocol] = v1;

        if (mat == 2) {
            // column sums over this warp's 16 rows (bias handled at init)
            float s0 = acc[nt][0] + acc[nt][2];
            float s1 = acc[nt][1] + acc[nt][3];
#pragma unroll
            for (int o = 4; o < 32; o <<= 1) {
                s0 += __shfl_xor_sync(0xffffffffu, s0, o);
                s1 += __shfl_xor_sync(0xffffffffu, s1, o);
            }
            if (r == 0) {
                atomicAdd(&g_Vsum[bb * D_ + ocol], s0);
                atomicAdd(&g_Vsum[bb * D_ + ocol + 1], s1);
            }
        }
    }
}

// ---------------------------------------------------------------------------
// Kernel 2: windowed attention combine. One warp per (b, i).
// out[i] = [ e0*Vsum + sum_w (e_w - e0)*V[j_w] ] / [ sum_w e_w + e0*(S - n_valid) ]
// ---------------------------------------------------------------------------
__global__ __launch_bounds__(256) void attn_kernel(float* __restrict__ out)
{
    const int gw = (blockIdx.x * blockDim.x + threadIdx.x) >> 5;
    const int lane = threadIdx.x & 31;
    if (gw >= B_ * S_) return;

    const int b = gw >> 12;
    const int i = gw & (S_ - 1);

    const float* Qr = g_Q + (size_t)gw * D_;
    const float q0 = Qr[lane];
    const float q1 = Qr[lane + 32];

    float c[WIN_];
    bool valid[WIN_];
    int jv[WIN_];
    int nv = 0;
    float cmax = 0.f;

#pragma unroll
    for (int w = 0; w < WIN_; w++) {
        const int j = i + DIL_ * (w - WIN_ / 2);
        jv[w] = j;
        valid[w] = (j >= 0) && (j < S_);
        float p = 0.f;
        if (valid[w]) {
            const float* Kr = g_K + ((size_t)b * S_ + j) * D_;
            p = q0 * Kr[lane] + q1 * Kr[lane + 32];
#pragma unroll
            for (int o = 16; o > 0; o >>= 1)
                p += __shfl_xor_sync(0xffffffffu, p, o);
            nv++;
            cmax = fmaxf(cmax, p);
        }
        c[w] = p;
    }

    const float vs0 = g_Vsum[b * D_ + lane];
    const float vs1 = g_Vsum[b * D_ + lane + 32];

    const float e0 = expf(-cmax);
    float denom = e0 * (float)(S_ - nv);
    float acc0 = e0 * vs0;
    float acc1 = e0 * vs1;

#pragma unroll
    for (int w = 0; w < WIN_; w++) {
        if (valid[w]) {
            const float ew = expf(c[w] - cmax);
            denom += ew;
            const float f = ew - e0;
            const float* Vr = g_V + ((size_t)b * S_ + jv[w]) * D_;
            acc0 = fmaf(f, Vr[lane], acc0);
            acc1 = fmaf(f, Vr[lane + 32], acc1);
        }
    }

    const float inv = 1.f / denom;
    out[(size_t)gw * D_ + lane] = acc0 * inv;
    out[(size_t)gw * D_ + lane + 32] = acc1 * inv;
}

// ---------------------------------------------------------------------------
extern "C" void kernel_launch(void* const* d_in, const int* in_sizes, int n_in,
                              void* d_out, int out_size)
{
    const float* x  = (const float*)d_in[0];
    const float* Wq = (const float*)d_in[1];
    const float* bq = (const float*)d_in[2];
    const float* Wk = (const float*)d_in[3];
    const float* bk = (const float*)d_in[4];
    const float* Wv = (const float*)d_in[5];
    const float* bv = (const float*)d_in[6];
    float* out = (float*)d_out;

    static int configured = 0;
    if (!configured) {
        cudaFuncSetAttribute(qkv_gemm_merged,
                             cudaFuncAttributeMaxDynamicSharedMemorySize,
                             SMEM_U32 * 4);
        configured = 1;
    }

    wsplit_kernel<<<((E_ / 2) * 192 + 255) / 256, 256>>>(Wq, Wk, Wv, bv);

    qkv_gemm_merged<<<(B_ * S_) / BM, 512, SMEM_U32 * 4>>>(x, bq, bk, bv);

    const int warps = B_ * S_;
    attn_kernel<<<(warps * 32 + 255) / 256, 256>>>(out);
}